// round 2
// baseline (speedup 1.0000x reference)
#include <cuda_runtime.h>
#include <cuda_bf16.h>

// Problem shapes (fixed for NeuronGemma4VisionPooler_74792560493244):
//   hidden_states       f32 [B=8, S=4096, H=1152]
//   pixel_position_ids  i32 [B, S, 2]   (x, y)
//   padding_positions   bool[B, S]
//   output_length       L = 256, k = sqrt(S/L) = 4, k_sq = 16
// Output: pooled f32 [B, L, H] (+ mask [B, L] as 0/1 floats if out_size covers it)

#define BB 8
#define SS 4096
#define HH 1152
#define LL 256
#define KK 4
#define CAP 64   // max recorded tokens per output bin (expected 16)

__device__ int g_maxx[BB];
__device__ int g_count[BB * LL];
__device__ int g_inv[BB * LL * CAP];

// --- K1: zero counters (fused) + per-batch max of clamped x ---
__global__ void k_maxx(const int* __restrict__ pos) {
    int b = blockIdx.x;
    // fused counter zeroing: 8 blocks x 256 threads == 2048 == BB*LL
    g_count[b * 256 + threadIdx.x] = 0;

    int m = 0;
    for (int s = threadIdx.x; s < SS; s += blockDim.x) {
        int x = pos[(b * SS + s) * 2];
        if (x > m) m = x;               // clip(x,0): negatives lose to m>=0
    }
    #pragma unroll
    for (int o = 16; o; o >>= 1) m = max(m, __shfl_xor_sync(0xffffffffu, m, o));
    __shared__ int sm[32];
    if ((threadIdx.x & 31) == 0) sm[threadIdx.x >> 5] = m;
    __syncthreads();
    if (threadIdx.x < 32) {
        int nw = blockDim.x >> 5;
        int v = (threadIdx.x < nw) ? sm[threadIdx.x] : 0;
        #pragma unroll
        for (int o = 16; o; o >>= 1) v = max(v, __shfl_xor_sync(0xffffffffu, v, o));
        if (threadIdx.x == 0) g_maxx[b] = v;
    }
}

// --- K2: compute bin per token, build inverse lists ---
__global__ void k_idx(const int* __restrict__ pos) {
    int i = blockIdx.x * blockDim.x + threadIdx.x;   // token id in [0, B*S)
    if (i >= BB * SS) return;
    int b = i >> 12;                                  // /SS
    int2 p = ((const int2*)pos)[i];
    int x = max(p.x, 0);
    int y = max(p.y, 0);
    int mx = g_maxx[b] + 1;                           // ref: max(clamped)+1
    int idx = x / KK + (mx / KK) * (y / KK);          // floor div, non-negative
    if (idx < LL) {                                   // one_hot drops idx>=L
        int slot = atomicAdd(&g_count[b * LL + idx], 1);
        if (slot < CAP) g_inv[(b * LL + idx) * CAP + slot] = i - (b << 12);
    }
}

// --- K3: gather-reduce rows per output bin ---
__global__ void __launch_bounds__(288, 4)
k_pool(const float* __restrict__ hs, const unsigned char* __restrict__ pad,
       float* __restrict__ out, int write_mask) {
    int b = blockIdx.x >> 8;
    int l = blockIdx.x & (LL - 1);
    int cnt = g_count[b * LL + l];
    int n = min(cnt, CAP);
    const int t = threadIdx.x;                        // 0..287, H/4 lanes
    const float4* __restrict__ hs4 = (const float4*)hs;

    float4 acc = make_float4(0.f, 0.f, 0.f, 0.f);
    const int base = (b * LL + l) * CAP;
    for (int j = 0; j < n; j++) {
        int s = g_inv[base + j];
        if (pad[b * SS + s]) continue;                // zeroed padded rows
        float4 v = __ldg(&hs4[(size_t)(b * SS + s) * (HH / 4) + t]);
        acc.x += v.x; acc.y += v.y; acc.z += v.z; acc.w += v.w;
    }
    const float scale = 2.1213203435596424f;          // sqrt(1152)/16
    acc.x *= scale; acc.y *= scale; acc.z *= scale; acc.w *= scale;
    ((float4*)out)[(size_t)(b * LL + l) * (HH / 4) + t] = acc;

    if (write_mask && t == 0)
        out[(size_t)BB * LL * HH + b * LL + l] = (cnt > 0) ? 1.0f : 0.0f;
}

extern "C" void kernel_launch(void* const* d_in, const int* in_sizes, int n_in,
                              void* d_out, int out_size) {
    const float*         hs  = (const float*)d_in[0];
    const int*           pos = (const int*)d_in[1];
    const unsigned char* pad = (const unsigned char*)d_in[2];
    float* out = (float*)d_out;

    int write_mask = (out_size >= BB * LL * HH + BB * LL) ? 1 : 0;

    k_maxx<<<BB, 256>>>(pos);
    k_idx<<<(BB * SS + 255) / 256, 256>>>(pos);
    k_pool<<<BB * LL, 288>>>(hs, pad, out, write_mask);
}

// round 3
// speedup vs baseline: 1.0586x; 1.0586x over previous
#include <cuda_runtime.h>
#include <cuda_bf16.h>

// NeuronGemma4VisionPooler: B=8, S=4096, H=1152, L=256, k=4, k_sq=16
// hidden_states f32 [B,S,H]; pixel_position_ids i32 [B,S,2];
// padding_positions bool [B,S]; out: pooled f32 [B,L,H] (+ mask [B,L] f32)

#define BB 8
#define SS 4096
#define HH 1152
#define LL 256
#define KK 4
#define CAP 64   // max recorded tokens per output bin (expected 16)

__device__ int g_count[BB * LL];            // packed: [total<<16 | appended]
__device__ int g_inv[BB * LL * CAP];

// --- K1 (fused prologue): per-batch max_x reduce + token binning ---
// One block per batch. Shared-memory packed counters, no global atomics.
__global__ void __launch_bounds__(1024)
k_prep(const int* __restrict__ pos, const unsigned char* __restrict__ pad) {
    const int b = blockIdx.x;
    const int t = threadIdx.x;
    __shared__ int s_cnt[LL];
    __shared__ int s_red[32];
    __shared__ int s_mx;

    // zero counters (1024 threads cover 256)
    if (t < LL) s_cnt[t] = 0;

    // pass 1: max over clamped x
    const int2* __restrict__ p2 = (const int2*)(pos + (size_t)b * SS * 2);
    int m = 0;
    #pragma unroll
    for (int s = t; s < SS; s += 1024) {
        int x = p2[s].x;
        if (x > m) m = x;                       // clip(x,0): negatives lose
    }
    #pragma unroll
    for (int o = 16; o; o >>= 1) m = max(m, __shfl_xor_sync(0xffffffffu, m, o));
    if ((t & 31) == 0) s_red[t >> 5] = m;
    __syncthreads();
    if (t < 32) {
        int v = s_red[t];
        #pragma unroll
        for (int o = 16; o; o >>= 1) v = max(v, __shfl_xor_sync(0xffffffffu, v, o));
        if (t == 0) s_mx = v + 1;               // ref: max(clamped)+1
    }
    __syncthreads();
    const int mxk = s_mx / KK;

    // pass 2: bin tokens (pos now in L1/L2)
    const unsigned char* __restrict__ pd = pad + (size_t)b * SS;
    #pragma unroll
    for (int s = t; s < SS; s += 1024) {
        int2 p = p2[s];
        int x = max(p.x, 0);
        int y = max(p.y, 0);
        int idx = x / KK + mxk * (y / KK);
        if (idx < LL) {                          // one_hot drops idx >= L
            if (pd[s]) {
                atomicAdd(&s_cnt[idx], 0x10000); // total only (mask)
            } else {
                int old = atomicAdd(&s_cnt[idx], 0x10001);
                int slot = old & 0xffff;
                if (slot < CAP)
                    g_inv[(b * LL + idx) * CAP + slot] = s;
            }
        }
    }
    __syncthreads();
    if (t < LL) g_count[b * LL + t] = s_cnt[t];
}

// --- K2: gather-reduce rows per output bin ---
__global__ void __launch_bounds__(288, 4)
k_pool(const float* __restrict__ hs, float* __restrict__ out, int write_mask) {
    const int b = blockIdx.x >> 8;
    const int l = blockIdx.x & (LL - 1);
    const int packed = g_count[b * LL + l];
    const int n = min(packed & 0xffff, CAP);
    const int t = threadIdx.x;                   // 0..287 = H/4 lanes
    const float4* __restrict__ hs4 =
        (const float4*)hs + (size_t)b * SS * (HH / 4);

    __shared__ int sidx[CAP];
    if (t < n) sidx[t] = g_inv[(b * LL + l) * CAP + t];
    __syncthreads();

    float4 acc = make_float4(0.f, 0.f, 0.f, 0.f);
    if (n == 16) {
        // common case: fully unrolled -> 16 independent LDG.128 in flight
        #pragma unroll
        for (int j = 0; j < 16; j++) {
            float4 v = __ldg(&hs4[(size_t)sidx[j] * (HH / 4) + t]);
            acc.x += v.x; acc.y += v.y; acc.z += v.z; acc.w += v.w;
        }
    } else {
        for (int j = 0; j < n; j++) {
            float4 v = __ldg(&hs4[(size_t)sidx[j] * (HH / 4) + t]);
            acc.x += v.x; acc.y += v.y; acc.z += v.z; acc.w += v.w;
        }
    }
    const float scale = 2.1213203435596424f;     // sqrt(1152)/16
    acc.x *= scale; acc.y *= scale; acc.z *= scale; acc.w *= scale;
    ((float4*)out)[(size_t)(b * LL + l) * (HH / 4) + t] = acc;

    if (write_mask && t == 0)
        out[(size_t)BB * LL * HH + b * LL + l] =
            ((packed >> 16) > 0) ? 1.0f : 0.0f;
}

extern "C" void kernel_launch(void* const* d_in, const int* in_sizes, int n_in,
                              void* d_out, int out_size) {
    const float*         hs  = (const float*)d_in[0];
    const int*           pos = (const int*)d_in[1];
    const unsigned char* pad = (const unsigned char*)d_in[2];
    float* out = (float*)d_out;

    int write_mask = (out_size >= BB * LL * HH + BB * LL) ? 1 : 0;

    k_prep<<<BB, 1024>>>(pos, pad);
    k_pool<<<BB * LL, 288>>>(hs, out, write_mask);
}

// round 7
// speedup vs baseline: 1.1102x; 1.0488x over previous
#include <cuda_runtime.h>
#include <cuda_bf16.h>

// NeuronGemma4VisionPooler: B=8, S=4096, H=1152, L=256, k=4, k_sq=16
// hidden_states f32 [B,S,H]; pixel_position_ids i32 [B,S,2];
// padding_positions bool [B,S]; out: pooled f32 [B,L,H] (+ mask [B,L] f32)

#define BB 8
#define SS 4096
#define HH 1152
#define LL 256
#define KK 4
#define CAP 64   // max recorded tokens per output bin (expected 16)

// Invariant: g_count is all-zero at entry to kernel_launch.
// (.bss zero at module load for the 1st call; k_pool resets it every call.)
__device__ int g_count[BB * LL];            // packed: [total<<16 | appended]
__device__ int g_inv[BB * LL * CAP];

// --- K1: parallel prologue. 8 blocks per batch (64 total).
// Each block: redundant max_x reduce over its whole batch (L2-resident),
// then bins exactly its 512-token slice via global packed atomics.
__global__ void __launch_bounds__(512)
k_prep(const int* __restrict__ pos, const unsigned char* __restrict__ pad) {
    const int b     = blockIdx.x >> 3;
    const int slice = blockIdx.x & 7;
    const int t     = threadIdx.x;
    const int2* __restrict__ p2 = (const int2*)pos + (size_t)b * SS;

    // max over clamped x for the whole batch
    int m = 0;
    #pragma unroll
    for (int s = t; s < SS; s += 512) {
        int x = p2[s].x;
        if (x > m) m = x;                      // clip(x,0): negatives lose
    }
    #pragma unroll
    for (int o = 16; o; o >>= 1) m = max(m, __shfl_xor_sync(0xffffffffu, m, o));
    __shared__ int s_red[16];
    __shared__ int s_mxk;
    if ((t & 31) == 0) s_red[t >> 5] = m;
    __syncthreads();
    if (t < 16) {
        int v = s_red[t];
        #pragma unroll
        for (int o = 8; o; o >>= 1) v = max(v, __shfl_xor_sync(0xffffu, v, o));
        if (t == 0) s_mxk = (v + 1) / KK;       // (max_clamped+1)/k
    }
    __syncthreads();
    const int mxk = s_mxk;

    // bin this block's 512-token slice (one token per thread)
    const int s = slice * 512 + t;
    int2 p = p2[s];
    int x = max(p.x, 0);
    int y = max(p.y, 0);
    int idx = x / KK + mxk * (y / KK);
    if (idx < LL) {                             // one_hot drops idx >= L
        if (pad[(size_t)b * SS + s]) {
            atomicAdd(&g_count[b * LL + idx], 0x10000);   // total only (mask)
        } else {
            int old = atomicAdd(&g_count[b * LL + idx], 0x10001);
            int slot = old & 0xffff;
            if (slot < CAP)
                g_inv[(b * LL + idx) * CAP + slot] = s;
        }
    }
}

// --- K2: gather-reduce rows per output bin; resets its counter for the
// next kernel_launch invocation (graph replay safety).
__global__ void __launch_bounds__(288, 5)
k_pool(const float* __restrict__ hs, float* __restrict__ out, int write_mask) {
    const int b = blockIdx.x >> 8;
    const int l = blockIdx.x & (LL - 1);
    const int t = threadIdx.x;                  // 0..287 = H/4 lanes
    const int packed = g_count[b * LL + l];
    const int n = min(packed & 0xffff, CAP);
    const float4* __restrict__ hs4 =
        (const float4*)hs + (size_t)b * SS * (HH / 4);

    __shared__ int sidx[CAP];
    if (t < n) sidx[t] = g_inv[(b * LL + l) * CAP + t];
    __syncthreads();
    if (t == 0) g_count[b * LL + l] = 0;        // reset for next launch

    float4 acc = make_float4(0.f, 0.f, 0.f, 0.f);
    if (n == 16) {
        // common case: fully unrolled, loads batched in flight
        #pragma unroll
        for (int j = 0; j < 16; j++) {
            float4 v = __ldg(&hs4[(size_t)sidx[j] * (HH / 4) + t]);
            acc.x += v.x; acc.y += v.y; acc.z += v.z; acc.w += v.w;
        }
    } else {
        for (int j = 0; j < n; j++) {
            float4 v = __ldg(&hs4[(size_t)sidx[j] * (HH / 4) + t]);
            acc.x += v.x; acc.y += v.y; acc.z += v.z; acc.w += v.w;
        }
    }
    const float scale = 2.1213203435596424f;    // sqrt(1152)/16
    acc.x *= scale; acc.y *= scale; acc.z *= scale; acc.w *= scale;
    ((float4*)out)[(size_t)(b * LL + l) * (HH / 4) + t] = acc;

    if (write_mask && t == 0)
        out[(size_t)BB * LL * HH + b * LL + l] =
            ((packed >> 16) > 0) ? 1.0f : 0.0f;
}

extern "C" void kernel_launch(void* const* d_in, const int* in_sizes, int n_in,
                              void* d_out, int out_size) {
    const float*         hs  = (const float*)d_in[0];
    const int*           pos = (const int*)d_in[1];
    const unsigned char* pad = (const unsigned char*)d_in[2];
    float* out = (float*)d_out;

    int write_mask = (out_size >= BB * LL * HH + BB * LL) ? 1 : 0;

    k_prep<<<BB * 8, 512>>>(pos, pad);
    k_pool<<<BB * LL, 288>>>(hs, out, write_mask);
}